// round 2
// baseline (speedup 1.0000x reference)
#include <cuda_runtime.h>
#include <stdint.h>

#define B 8192
#define D 512
#define ROWS_PER_BLOCK 4
#define AM_THREADS 256

__device__ int      g_idx_p[B];
__device__ int      g_idx_n[B];
__device__ float    g_rowloss[B];
__device__ uint32_t g_one = 1;   // opaque 1: forces IMAD instead of IADD3

// ---------------- compile-time threefry for key derivation ----------------
struct K2 { uint32_t a, b; };
constexpr uint32_t rotl_c(uint32_t x, int r) { return (x << r) | (x >> (32 - r)); }
constexpr K2 tf_c(uint32_t k0, uint32_t k1, uint32_t x0, uint32_t x1) {
    uint32_t ks2 = k0 ^ k1 ^ 0x1BD11BDAu;
    x0 += k0; x1 += k1;
    const int RA[4] = {13, 15, 26, 6};
    const int RB[4] = {17, 29, 16, 24};
    for (int i = 0; i < 4; i++) { x0 += x1; x1 = rotl_c(x1, RA[i]); x1 ^= x0; }
    x0 += k1;  x1 += ks2 + 1u;
    for (int i = 0; i < 4; i++) { x0 += x1; x1 = rotl_c(x1, RB[i]); x1 ^= x0; }
    x0 += ks2; x1 += k0 + 2u;
    for (int i = 0; i < 4; i++) { x0 += x1; x1 = rotl_c(x1, RA[i]); x1 ^= x0; }
    x0 += k0;  x1 += k1 + 3u;
    for (int i = 0; i < 4; i++) { x0 += x1; x1 = rotl_c(x1, RB[i]); x1 ^= x0; }
    x0 += k1;  x1 += ks2 + 4u;
    for (int i = 0; i < 4; i++) { x0 += x1; x1 = rotl_c(x1, RA[i]); x1 ^= x0; }
    x0 += ks2; x1 += k0 + 5u;
    return K2{x0, x1};
}

// kp = split(key(42))[0], kn = split(key(42))[1]  (partitionable threefry)
constexpr K2 KP = tf_c(0u, 42u, 0u, 0u);
constexpr K2 KN = tf_c(0u, 42u, 0u, 1u);

constexpr uint32_t KP0 = KP.a, KP1 = KP.b, KPS = KP0 ^ KP1 ^ 0x1BD11BDAu;
constexpr uint32_t KN0 = KN.a, KN1 = KN.b, KNS = KN0 ^ KN1 ^ 0x1BD11BDAu;

// The 8 injection constants per key side.
constexpr uint32_t PC[8] = {KP0, KP1, KPS + 1u, KPS, KP0 + 2u, KP1 + 3u, KPS + 4u, KP0 + 5u};
constexpr uint32_t NC[8] = {KN0, KN1, KNS + 1u, KNS, KN0 + 2u, KN1 + 3u, KNS + 4u, KN0 + 5u};

// d = a*one + c  -> guaranteed IMAD on the fma pipe (one is opaque)
#define MADD(d, a, c) asm("mad.lo.u32 %0, %1, %2, %3;" : "=r"(d) : "r"(a), "r"(one), "r"(c))
// d = pos01*IMM + c  -> IMAD-imm select between key sides (fma pipe)
#define MSEL(d, IMM, c) asm("mad.lo.u32 %0, %1, %2, %3;" : "=r"(d) : "r"(pos01), "n"((int)(IMM)), "r"(c))

#define RND(ra) { MADD(x0, x1, x0); x1 = __funnelshift_l(x1, x1, (ra)); x1 ^= x0; }

__global__ void __launch_bounds__(AM_THREADS) argmax_kernel(const int* __restrict__ labels) {
    __shared__ uint8_t slab[B];             // 8 KB
    __shared__ unsigned long long sredp[AM_THREADS / 32];
    __shared__ unsigned long long sredn[AM_THREADS / 32];

    const int tid = threadIdx.x;
    for (int i = tid; i < B; i += AM_THREADS) slab[i] = (uint8_t)labels[i];
    __syncthreads();

    const uint32_t one = g_one;
    // KN-side base constants kept in registers (loop-invariant)
    uint32_t n0 = NC[0], n1 = NC[1], n2 = NC[2], n3 = NC[3];
    uint32_t n4 = NC[4], n5 = NC[5], n6 = NC[6], n7 = NC[7];

    const int r0 = blockIdx.x * ROWS_PER_BLOCK;

    for (int rr = 0; rr < ROWS_PER_BLOCK; rr++) {
        const int r = r0 + rr;
        const uint32_t myl = slab[r];
        const uint32_t base_tid = ((uint32_t)r << 13) + (uint32_t)tid;

        uint32_t bp = 0u, bn = 0u;      // masked-bits maxima
        uint32_t kbp = 0u, kbn = 0u;    // iteration index of the max

        #pragma unroll 4
        for (uint32_t k = 0; k < B / AM_THREADS; k++) {
            const uint32_t lab = slab[tid + k * AM_THREADS];
            const bool pos = (lab == myl);
            const uint32_t pos01 = pos ? 1u : 0u;

            uint32_t sk0, sk1, s2, s3, s4, s5, s6, s7;
            MSEL(sk0, PC[0] - NC[0], n0);
            MSEL(sk1, PC[1] - NC[1], n1);
            MSEL(s2,  PC[2] - NC[2], n2);
            MSEL(s3,  PC[3] - NC[3], n3);
            MSEL(s4,  PC[4] - NC[4], n4);
            MSEL(s5,  PC[5] - NC[5], n5);
            MSEL(s6,  PC[6] - NC[6], n6);
            MSEL(s7,  PC[7] - NC[7], n7);

            uint32_t x0 = sk0;
            uint32_t x1 = sk1 + base_tid + k * AM_THREADS;   // IADD3

            RND(13) RND(15) RND(26) RND(6)
            MADD(x0, sk1, x0); MADD(x1, s2, x1);
            RND(17) RND(29) RND(16) RND(24)
            MADD(x0, s3, x0);  MADD(x1, s4, x1);
            RND(13) RND(15) RND(26) RND(6)
            MADD(x0, sk0, x0); MADD(x1, s5, x1);
            RND(17) RND(29) RND(16) RND(24)
            MADD(x0, sk1, x0); MADD(x1, s6, x1);
            RND(13) RND(15) RND(26) RND(6)
            MADD(x0, s3, x0);  MADD(x1, s7, x1);

            const uint32_t v = (x0 ^ x1) & 0xFFFFFE00u;  // single LOP3; top-23 bits
            if (pos) { if (v > bp) { bp = v; kbp = k; } }
            else     { if (v > bn) { bn = v; kbn = k; } }
        }

        // pack (bits, index) for cross-thread argmax with first-index tie-break
        const uint32_t cp = (uint32_t)tid + kbp * AM_THREADS;
        const uint32_t cn = (uint32_t)tid + kbn * AM_THREADS;
        unsigned long long pkp = ((unsigned long long)bp << 13) | (unsigned long long)(8191u - cp);
        unsigned long long pkn = ((unsigned long long)bn << 13) | (unsigned long long)(8191u - cn);

        for (int off = 16; off > 0; off >>= 1) {
            unsigned long long o;
            o = __shfl_down_sync(0xFFFFFFFFu, pkp, off); if (o > pkp) pkp = o;
            o = __shfl_down_sync(0xFFFFFFFFu, pkn, off); if (o > pkn) pkn = o;
        }
        const int w = tid >> 5;
        if ((tid & 31) == 0) { sredp[w] = pkp; sredn[w] = pkn; }
        __syncthreads();
        if (tid == 0) {
            unsigned long long mp = sredp[0], mn = sredn[0];
            #pragma unroll
            for (int i = 1; i < AM_THREADS / 32; i++) {
                if (sredp[i] > mp) mp = sredp[i];
                if (sredn[i] > mn) mn = sredn[i];
            }
            g_idx_p[r] = 8191 - (int)(mp & 0x1FFFull);
            g_idx_n[r] = 8191 - (int)(mn & 0x1FFFull);
        }
        __syncthreads();
    }
}

// Per-row hinge: cos(a,p) - cos(a,n) + margin, clamped at 0.
__global__ void __launch_bounds__(128) loss_kernel(const float* __restrict__ pred) {
    __shared__ float sred[5][4];
    const int r = blockIdx.x;
    const int tid = threadIdx.x;
    const int ip  = g_idx_p[r];
    const int in_ = g_idx_n[r];
    const float* __restrict__ a = pred + (size_t)r   * D;
    const float* __restrict__ p = pred + (size_t)ip  * D;
    const float* __restrict__ n = pred + (size_t)in_ * D;

    float saa = 0.f, spp = 0.f, snn = 0.f, sap = 0.f, san = 0.f;
    for (int j = tid; j < D; j += 128) {
        const float av = a[j], pv = p[j], nv = n[j];
        saa += av * av; spp += pv * pv; snn += nv * nv;
        sap += av * pv; san += av * nv;
    }
    for (int off = 16; off > 0; off >>= 1) {
        saa += __shfl_down_sync(0xFFFFFFFFu, saa, off);
        spp += __shfl_down_sync(0xFFFFFFFFu, spp, off);
        snn += __shfl_down_sync(0xFFFFFFFFu, snn, off);
        sap += __shfl_down_sync(0xFFFFFFFFu, sap, off);
        san += __shfl_down_sync(0xFFFFFFFFu, san, off);
    }
    const int w = tid >> 5;
    if ((tid & 31) == 0) {
        sred[0][w] = saa; sred[1][w] = spp; sred[2][w] = snn;
        sred[3][w] = sap; sred[4][w] = san;
    }
    __syncthreads();
    if (tid == 0) {
        float t0 = 0, t1 = 0, t2 = 0, t3 = 0, t4 = 0;
        #pragma unroll
        for (int i = 0; i < 4; i++) {
            t0 += sred[0][i]; t1 += sred[1][i]; t2 += sred[2][i];
            t3 += sred[3][i]; t4 += sred[4][i];
        }
        const float na = fmaxf(sqrtf(t0), 1e-6f);
        const float np = fmaxf(sqrtf(t1), 1e-6f);
        const float nn = fmaxf(sqrtf(t2), 1e-6f);
        g_rowloss[r] = fmaxf(t3 / (na * np) - t4 / (na * nn) + 0.1f, 0.0f);
    }
}

__global__ void __launch_bounds__(1024) reduce_kernel(float* __restrict__ out) {
    __shared__ float s[1024];
    const int tid = threadIdx.x;
    float v = 0.f;
    for (int i = tid; i < B; i += 1024) v += g_rowloss[i];
    s[tid] = v;
    __syncthreads();
    for (int st = 512; st > 0; st >>= 1) {
        if (tid < st) s[tid] += s[tid + st];
        __syncthreads();
    }
    if (tid == 0) out[0] = s[0] * (1.0f / (float)B);
}

extern "C" void kernel_launch(void* const* d_in, const int* in_sizes, int n_in,
                              void* d_out, int out_size) {
    const float* pred   = (const float*)d_in[0];
    const int*   labels = (const int*)d_in[1];
    float* out = (float*)d_out;

    argmax_kernel<<<B / ROWS_PER_BLOCK, AM_THREADS>>>(labels);
    loss_kernel<<<B, 128>>>(pred);
    reduce_kernel<<<1, 1024>>>(out);
}

// round 5
// speedup vs baseline: 1.0359x; 1.0359x over previous
#include <cuda_runtime.h>
#include <stdint.h>

#define B 8192
#define D 512
#define ROWS_PER_BLOCK 4
#define AM_THREADS 256

__device__ int      g_idx_p[B];
__device__ int      g_idx_n[B];
__device__ float    g_rowloss[B];
__device__ uint32_t g_one = 1;   // opaque 1: forces IMAD (fma pipe) instead of IADD3

// ---------------- compile-time threefry for key derivation ----------------
struct K2 { uint32_t a, b; };
constexpr uint32_t rotl_c(uint32_t x, int r) { return (x << r) | (x >> (32 - r)); }
constexpr K2 tf_c(uint32_t k0, uint32_t k1, uint32_t x0, uint32_t x1) {
    uint32_t ks2 = k0 ^ k1 ^ 0x1BD11BDAu;
    x0 += k0; x1 += k1;
    const int RA[4] = {13, 15, 26, 6};
    const int RB[4] = {17, 29, 16, 24};
    for (int i = 0; i < 4; i++) { x0 += x1; x1 = rotl_c(x1, RA[i]); x1 ^= x0; }
    x0 += k1;  x1 += ks2 + 1u;
    for (int i = 0; i < 4; i++) { x0 += x1; x1 = rotl_c(x1, RB[i]); x1 ^= x0; }
    x0 += ks2; x1 += k0 + 2u;
    for (int i = 0; i < 4; i++) { x0 += x1; x1 = rotl_c(x1, RA[i]); x1 ^= x0; }
    x0 += k0;  x1 += k1 + 3u;
    for (int i = 0; i < 4; i++) { x0 += x1; x1 = rotl_c(x1, RB[i]); x1 ^= x0; }
    x0 += k1;  x1 += ks2 + 4u;
    for (int i = 0; i < 4; i++) { x0 += x1; x1 = rotl_c(x1, RA[i]); x1 ^= x0; }
    x0 += ks2; x1 += k0 + 5u;
    return K2{x0, x1};
}

constexpr K2 KP = tf_c(0u, 42u, 0u, 0u);   // split(key(42))[0]
constexpr K2 KN = tf_c(0u, 42u, 0u, 1u);   // split(key(42))[1]

constexpr uint32_t KP0 = KP.a, KP1 = KP.b, KPS = KP0 ^ KP1 ^ 0x1BD11BDAu;
constexpr uint32_t KN0 = KN.a, KN1 = KN.b, KNS = KN0 ^ KN1 ^ 0x1BD11BDAu;

// 8 injection constants per key side (round constants folded in).
constexpr uint32_t PC0 = KP0,      PC1 = KP1,      PC2 = KPS + 1u, PC3 = KPS;
constexpr uint32_t PC4 = KP0 + 2u, PC5 = KP1 + 3u, PC6 = KPS + 4u, PC7 = KP0 + 5u;
constexpr uint32_t NC0 = KN0,      NC1 = KN1,      NC2 = KNS + 1u, NC3 = KNS;
constexpr uint32_t NC4 = KN0 + 2u, NC5 = KN1 + 3u, NC6 = KNS + 4u, NC7 = KN0 + 5u;

// d = a*one + c  -> IMAD on the fma pipe
#define MADD(d, a, c) asm("mad.lo.u32 %0, %1, %2, %3;" : "=r"(d) : "r"(a), "r"(one), "r"(c))
// d = pos01*IMM + c  -> IMAD-imm key-side select (fma pipe)
#define MSEL(d, IMM, c) asm("mad.lo.u32 %0, %1, %2, %3;" : "=r"(d) : "r"(pos01), "n"((int)(IMM)), "r"(c))

#define RND(ra) { MADD(x0, x1, x0); x1 = __funnelshift_l(x1, x1, (ra)); x1 ^= x0; }

// One threefry eval; returns (y0^y1) & 0xFFFFFE00 (top-23 gumbel-monotone bits).
__device__ __forceinline__ uint32_t tf_eval(
    uint32_t one, uint32_t pos01, uint32_t cnt,
    uint32_t n0, uint32_t n1, uint32_t n2, uint32_t n3,
    uint32_t n4, uint32_t n5, uint32_t n6, uint32_t n7)
{
    uint32_t sk0, sk1, s2, s3, s4, s5, s6, s7;
    MSEL(sk0, PC0 - NC0, n0);
    MSEL(sk1, PC1 - NC1, n1);
    MSEL(s2,  PC2 - NC2, n2);
    MSEL(s3,  PC3 - NC3, n3);
    MSEL(s4,  PC4 - NC4, n4);
    MSEL(s5,  PC5 - NC5, n5);
    MSEL(s6,  PC6 - NC6, n6);
    MSEL(s7,  PC7 - NC7, n7);

    uint32_t x0 = sk0;
    uint32_t x1;
    MADD(x1, sk1, cnt);                       // x1 = cnt + k1

    RND(13) RND(15) RND(26) RND(6)
    MADD(x0, sk1, x0); MADD(x1, s2, x1);
    RND(17) RND(29) RND(16) RND(24)
    MADD(x0, s3, x0);  MADD(x1, s4, x1);
    RND(13) RND(15) RND(26) RND(6)
    MADD(x0, sk0, x0); MADD(x1, s5, x1);
    RND(17) RND(29) RND(16) RND(24)
    MADD(x0, sk1, x0); MADD(x1, s6, x1);
    RND(13) RND(15) RND(26) RND(6)
    MADD(x0, s3, x0);  MADD(x1, s7, x1);

    return (x0 ^ x1) & 0xFFFFFE00u;
}

__global__ void __launch_bounds__(AM_THREADS) argmax_kernel(const int* __restrict__ labels) {
    __shared__ uint8_t slab[B];             // 8 KB
    __shared__ unsigned long long sredp[AM_THREADS / 32];
    __shared__ unsigned long long sredn[AM_THREADS / 32];

    const int tid = threadIdx.x;
    for (int i = tid; i < B; i += AM_THREADS) slab[i] = (uint8_t)labels[i];
    __syncthreads();

    const uint32_t one = g_one;
    const uint32_t n0 = NC0, n1 = NC1, n2 = NC2, n3 = NC3;
    const uint32_t n4 = NC4, n5 = NC5, n6 = NC6, n7 = NC7;

    const int r0 = blockIdx.x * ROWS_PER_BLOCK;

    for (int rr = 0; rr < ROWS_PER_BLOCK; rr++) {
        const int r = r0 + rr;
        const uint32_t myl = slab[r];
        const uint32_t base_tid = ((uint32_t)r << 13) + (uint32_t)tid;

        // Two independent chains: A covers cols tid+512k, B covers tid+256+512k.
        uint32_t bpA = 0u, bnA = 0u, bpB = 0u, bnB = 0u;   // packed (v | kinv<<4)
        uint32_t kinv = 15u << 4;
        uint32_t cbase = base_tid;

        #pragma unroll 4
        for (int k = 0; k < 16; k++) {
            const uint32_t labA = slab[tid + k * 512];
            const uint32_t labB = slab[tid + 256 + k * 512];
            const bool isPosA = (labA == myl);
            const bool isPosB = (labB == myl);
            {
                const uint32_t pos01 = isPosA ? 1u : 0u;
                const uint32_t v = tf_eval(one, pos01, cbase, n0,n1,n2,n3,n4,n5,n6,n7);
                uint32_t packed; MADD(packed, v, kinv);
                if (isPosA) { if (packed > bpA) bpA = packed; }
                else        { if (packed > bnA) bnA = packed; }
            }
            {
                const uint32_t pos01 = isPosB ? 1u : 0u;
                const uint32_t v = tf_eval(one, pos01, cbase + 256u, n0,n1,n2,n3,n4,n5,n6,n7);
                uint32_t packed; MADD(packed, v, kinv);
                if (isPosB) { if (packed > bpB) bpB = packed; }
                else        { if (packed > bnB) bnB = packed; }
            }
            kinv -= 16u;
            cbase += 512u;
        }

        // Decode per-chain accumulators -> u64 (v23 << 13) | (8191 - col)
        const uint32_t tu = (uint32_t)tid;
        auto dec = [&](uint32_t acc, uint32_t coff) -> unsigned long long {
            const uint32_t v23 = acc >> 9;
            const uint32_t k   = 15u - ((acc >> 4) & 15u);
            const uint32_t col = tu + coff + k * 512u;
            return ((unsigned long long)v23 << 13) | (unsigned long long)(8191u - col);
        };
        unsigned long long pkp = dec(bpA, 0u);
        { unsigned long long o = dec(bpB, 256u); if (o > pkp) pkp = o; }
        unsigned long long pkn = dec(bnA, 0u);
        { unsigned long long o = dec(bnB, 256u); if (o > pkn) pkn = o; }

        for (int off = 16; off > 0; off >>= 1) {
            unsigned long long o;
            o = __shfl_down_sync(0xFFFFFFFFu, pkp, off); if (o > pkp) pkp = o;
            o = __shfl_down_sync(0xFFFFFFFFu, pkn, off); if (o > pkn) pkn = o;
        }
        const int w = tid >> 5;
        if ((tid & 31) == 0) { sredp[w] = pkp; sredn[w] = pkn; }
        __syncthreads();
        if (tid == 0) {
            unsigned long long mp = sredp[0], mn = sredn[0];
            #pragma unroll
            for (int i = 1; i < AM_THREADS / 32; i++) {
                if (sredp[i] > mp) mp = sredp[i];
                if (sredn[i] > mn) mn = sredn[i];
            }
            g_idx_p[r] = 8191 - (int)(mp & 0x1FFFull);
            g_idx_n[r] = 8191 - (int)(mn & 0x1FFFull);
        }
        __syncthreads();
    }
}

// Per-row hinge: cos(a,p) - cos(a,n) + margin, clamped at 0.
__global__ void __launch_bounds__(128) loss_kernel(const float* __restrict__ pred) {
    __shared__ float sred[5][4];
    const int r = blockIdx.x;
    const int tid = threadIdx.x;
    const int ip  = g_idx_p[r];
    const int in_ = g_idx_n[r];
    const float* __restrict__ a = pred + (size_t)r   * D;
    const float* __restrict__ p = pred + (size_t)ip  * D;
    const float* __restrict__ n = pred + (size_t)in_ * D;

    float saa = 0.f, spp = 0.f, snn = 0.f, sap = 0.f, san = 0.f;
    for (int j = tid; j < D; j += 128) {
        const float av = a[j], pv = p[j], nv = n[j];
        saa += av * av; spp += pv * pv; snn += nv * nv;
        sap += av * pv; san += av * nv;
    }
    for (int off = 16; off > 0; off >>= 1) {
        saa += __shfl_down_sync(0xFFFFFFFFu, saa, off);
        spp += __shfl_down_sync(0xFFFFFFFFu, spp, off);
        snn += __shfl_down_sync(0xFFFFFFFFu, snn, off);
        sap += __shfl_down_sync(0xFFFFFFFFu, sap, off);
        san += __shfl_down_sync(0xFFFFFFFFu, san, off);
    }
    const int w = tid >> 5;
    if ((tid & 31) == 0) {
        sred[0][w] = saa; sred[1][w] = spp; sred[2][w] = snn;
        sred[3][w] = sap; sred[4][w] = san;
    }
    __syncthreads();
    if (tid == 0) {
        float t0 = 0, t1 = 0, t2 = 0, t3 = 0, t4 = 0;
        #pragma unroll
        for (int i = 0; i < 4; i++) {
            t0 += sred[0][i]; t1 += sred[1][i]; t2 += sred[2][i];
            t3 += sred[3][i]; t4 += sred[4][i];
        }
        const float na = fmaxf(sqrtf(t0), 1e-6f);
        const float np = fmaxf(sqrtf(t1), 1e-6f);
        const float nn = fmaxf(sqrtf(t2), 1e-6f);
        g_rowloss[r] = fmaxf(t3 / (na * np) - t4 / (na * nn) + 0.1f, 0.0f);
    }
}

__global__ void __launch_bounds__(1024) reduce_kernel(float* __restrict__ out) {
    __shared__ float s[1024];
    const int tid = threadIdx.x;
    float v = 0.f;
    for (int i = tid; i < B; i += 1024) v += g_rowloss[i];
    s[tid] = v;
    __syncthreads();
    for (int st = 512; st > 0; st >>= 1) {
        if (tid < st) s[tid] += s[tid + st];
        __syncthreads();
    }
    if (tid == 0) out[0] = s[0] * (1.0f / (float)B);
}

extern "C" void kernel_launch(void* const* d_in, const int* in_sizes, int n_in,
                              void* d_out, int out_size) {
    const float* pred   = (const float*)d_in[0];
    const int*   labels = (const int*)d_in[1];
    float* out = (float*)d_out;

    argmax_kernel<<<B / ROWS_PER_BLOCK, AM_THREADS>>>(labels);
    loss_kernel<<<B, 128>>>(pred);
    reduce_kernel<<<1, 1024>>>(out);
}

// round 6
// speedup vs baseline: 1.1027x; 1.0645x over previous
#include <cuda_runtime.h>
#include <stdint.h>

#define B 8192
#define NGROUPS (B / 4)
#define AM_THREADS 256
#define AM_GRID 592        /* 148 SMs * 4 resident blocks */
#define D 512

__device__ int      g_idx_p[B];
__device__ int      g_idx_n[B];
__device__ float    g_rowloss[B];
__device__ int      g_order[B];
__device__ uint32_t g_one = 1;   // opaque 1: forces IMAD (fma pipe)

// ---------------- compile-time threefry for key derivation ----------------
struct K2 { uint32_t a, b; };
constexpr uint32_t rotl_c(uint32_t x, int r) { return (x << r) | (x >> (32 - r)); }
constexpr K2 tf_c(uint32_t k0, uint32_t k1, uint32_t x0, uint32_t x1) {
    uint32_t ks2 = k0 ^ k1 ^ 0x1BD11BDAu;
    x0 += k0; x1 += k1;
    const int RA[4] = {13, 15, 26, 6};
    const int RB[4] = {17, 29, 16, 24};
    for (int i = 0; i < 4; i++) { x0 += x1; x1 = rotl_c(x1, RA[i]); x1 ^= x0; }
    x0 += k1;  x1 += ks2 + 1u;
    for (int i = 0; i < 4; i++) { x0 += x1; x1 = rotl_c(x1, RB[i]); x1 ^= x0; }
    x0 += ks2; x1 += k0 + 2u;
    for (int i = 0; i < 4; i++) { x0 += x1; x1 = rotl_c(x1, RA[i]); x1 ^= x0; }
    x0 += k0;  x1 += k1 + 3u;
    for (int i = 0; i < 4; i++) { x0 += x1; x1 = rotl_c(x1, RB[i]); x1 ^= x0; }
    x0 += k1;  x1 += ks2 + 4u;
    for (int i = 0; i < 4; i++) { x0 += x1; x1 = rotl_c(x1, RA[i]); x1 ^= x0; }
    x0 += ks2; x1 += k0 + 5u;
    return K2{x0, x1};
}

constexpr K2 KP = tf_c(0u, 42u, 0u, 0u);   // split(key(42))[0]
constexpr K2 KN = tf_c(0u, 42u, 0u, 1u);   // split(key(42))[1]

constexpr uint32_t KP0 = KP.a, KP1 = KP.b, KPS = KP0 ^ KP1 ^ 0x1BD11BDAu;
constexpr uint32_t KN0 = KN.a, KN1 = KN.b, KNS = KN0 ^ KN1 ^ 0x1BD11BDAu;

constexpr uint32_t PC0 = KP0,      PC1 = KP1,      PC2 = KPS + 1u, PC3 = KPS;
constexpr uint32_t PC4 = KP0 + 2u, PC5 = KP1 + 3u, PC6 = KPS + 4u, PC7 = KP0 + 5u;
constexpr uint32_t NC0 = KN0,      NC1 = KN1,      NC2 = KNS + 1u, NC3 = KNS;
constexpr uint32_t NC4 = KN0 + 2u, NC5 = KN1 + 3u, NC6 = KNS + 4u, NC7 = KN0 + 5u;

#define MADD(d, a, c) asm("mad.lo.u32 %0, %1, %2, %3;" : "=r"(d) : "r"(a), "r"(one), "r"(c))
#define MSEL(d, IMM, c) asm("mad.lo.u32 %0, %1, %2, %3;" : "=r"(d) : "r"(pos01), "n"((int)(IMM)), "r"(c))

// 4-chain interleaved threefry round pieces (chains a,b,c,d)
#define R4_ADD() { MADD(a0,a1,a0); MADD(b0,b1,b0); MADD(c0,c1,c0); MADD(d0,d1,d0); }
#define R4_ROT(ra) { \
    a1 = __funnelshift_l(a1,a1,(ra)); b1 = __funnelshift_l(b1,b1,(ra)); \
    c1 = __funnelshift_l(c1,c1,(ra)); d1 = __funnelshift_l(d1,d1,(ra)); \
    a1 ^= a0; b1 ^= b0; c1 ^= c0; d1 ^= d0; }
#define R4(ra) { R4_ADD() R4_ROT(ra) }
#define INJ4(p0, p1) { \
    MADD(a0,p0,a0); MADD(b0,p0,b0); MADD(c0,p0,c0); MADD(d0,p0,d0); \
    MADD(a1,p1,a1); MADD(b1,p1,b1); MADD(c1,p1,c1); MADD(d1,p1,d1); }

// scalar single-chain eval for the (rare) mixed-label fallback path
#define RND1(ra) { MADD(x0, x1, x0); x1 = __funnelshift_l(x1, x1, (ra)); x1 ^= x0; }
__device__ __forceinline__ uint32_t tf_eval1(
    uint32_t one, uint32_t pos01, uint32_t cnt,
    uint32_t n0, uint32_t n1, uint32_t n2, uint32_t n3,
    uint32_t n4, uint32_t n5, uint32_t n6, uint32_t n7)
{
    uint32_t sk0, sk1, s2, s3, s4, s5, s6, s7;
    MSEL(sk0, PC0 - NC0, n0); MSEL(sk1, PC1 - NC1, n1);
    MSEL(s2,  PC2 - NC2, n2); MSEL(s3,  PC3 - NC3, n3);
    MSEL(s4,  PC4 - NC4, n4); MSEL(s5,  PC5 - NC5, n5);
    MSEL(s6,  PC6 - NC6, n6); MSEL(s7,  PC7 - NC7, n7);
    uint32_t x0 = sk0, x1;
    MADD(x1, sk1, cnt);
    RND1(13) RND1(15) RND1(26) RND1(6)
    MADD(x0, sk1, x0); MADD(x1, s2, x1);
    RND1(17) RND1(29) RND1(16) RND1(24)
    MADD(x0, s3, x0);  MADD(x1, s4, x1);
    RND1(13) RND1(15) RND1(26) RND1(6)
    MADD(x0, sk0, x0); MADD(x1, s5, x1);
    RND1(17) RND1(29) RND1(16) RND1(24)
    MADD(x0, sk1, x0); MADD(x1, s6, x1);
    RND1(13) RND1(15) RND1(26) RND1(6)
    MADD(x0, s3, x0);  MADD(x1, s7, x1);
    return (x0 ^ x1) & 0xFFFFFE00u;
}

// ---------------- stable counting sort of rows by label (14 labels) --------
__global__ void __launch_bounds__(448) order_kernel(const int* __restrict__ labels) {
    __shared__ int counts[14];
    __shared__ int base[14];
    const int w = threadIdx.x >> 5;
    const int lane = threadIdx.x & 31;

    int cnt = 0;
    for (int i = lane; i < B; i += 32) cnt += (labels[i] == w) ? 1 : 0;
    for (int off = 16; off > 0; off >>= 1) cnt += __shfl_down_sync(0xFFFFFFFFu, cnt, off);
    if (lane == 0) counts[w] = cnt;
    __syncthreads();
    if (threadIdx.x == 0) {
        int acc = 0;
        for (int l = 0; l < 14; l++) { base[l] = acc; acc += counts[l]; }
    }
    __syncthreads();
    int pos = base[w];
    for (int i0 = 0; i0 < B; i0 += 32) {
        const int i = i0 + lane;
        const bool m = (labels[i] == w);
        const unsigned bal = __ballot_sync(0xFFFFFFFFu, m);
        if (m) {
            const int rank = __popc(bal & ((1u << lane) - 1u));
            g_order[pos + rank] = i;
        }
        pos += __popc(bal);
    }
}

// ---------------- argmax over gumbel-bit matrices -------------------------
__global__ void __launch_bounds__(AM_THREADS, 4) argmax_kernel(const int* __restrict__ labels) {
    __shared__ uint8_t slab[B];
    __shared__ unsigned long long sredp[AM_THREADS / 32];
    __shared__ unsigned long long sredn[AM_THREADS / 32];
    __shared__ int srows[4];

    const int tid = threadIdx.x;
    for (int i = tid; i < B; i += AM_THREADS) slab[i] = (uint8_t)labels[i];
    __syncthreads();

    const uint32_t one = g_one;
    const uint32_t n0 = NC0, n1 = NC1, n2 = NC2, n3 = NC3;
    const uint32_t n4 = NC4, n5 = NC5, n6 = NC6, n7 = NC7;

    for (int g = blockIdx.x; g < NGROUPS; g += AM_GRID) {
        if (tid < 4) srows[tid] = g_order[g * 4 + tid];
        __syncthreads();
        const int rA = srows[0], rB = srows[1], rC = srows[2], rD = srows[3];
        const uint32_t lA = slab[rA], lB = slab[rB], lC = slab[rC], lD = slab[rD];
        const bool uniform = (lA == lB) && (lA == lC) && (lA == lD);

        // per-chain packed accumulators: v[31:9] | kinv[8:4]
        uint32_t bpA = 0u, bnA = 0u, bpB = 0u, bnB = 0u;
        uint32_t bpC = 0u, bnC = 0u, bpD = 0u, bnD = 0u;

        if (uniform) {
            const uint32_t myl = lA;
            uint32_t cntA = ((uint32_t)rA << 13) + (uint32_t)tid;
            uint32_t cntB = ((uint32_t)rB << 13) + (uint32_t)tid;
            uint32_t cntC = ((uint32_t)rC << 13) + (uint32_t)tid;
            uint32_t cntD = ((uint32_t)rD << 13) + (uint32_t)tid;
            uint32_t kinv = 31u << 4;

            #pragma unroll 1
            for (int k = 0; k < 32; k++) {
                const uint32_t lab = slab[tid + k * AM_THREADS];
                const bool pos = (lab == myl);
                const uint32_t pos01 = pos ? 1u : 0u;

                uint32_t sk0, sk1, s2, s3, s4, s5, s6, s7;
                MSEL(sk0, PC0 - NC0, n0); MSEL(sk1, PC1 - NC1, n1);
                MSEL(s2,  PC2 - NC2, n2); MSEL(s3,  PC3 - NC3, n3);
                MSEL(s4,  PC4 - NC4, n4); MSEL(s5,  PC5 - NC5, n5);
                MSEL(s6,  PC6 - NC6, n6); MSEL(s7,  PC7 - NC7, n7);

                uint32_t a0, a1, b0, b1, c0, c1, d0, d1;
                MADD(a1, sk1, cntA); MADD(b1, sk1, cntB);
                MADD(c1, sk1, cntC); MADD(d1, sk1, cntD);
                // round 1: x0 = sk0 + x1 (folds the init)
                MADD(a0, a1, sk0); MADD(b0, b1, sk0);
                MADD(c0, c1, sk0); MADD(d0, d1, sk0);
                R4_ROT(13)
                R4(15) R4(26) R4(6)
                INJ4(sk1, s2)
                R4(17) R4(29) R4(16) R4(24)
                INJ4(s3, s4)
                R4(13) R4(15) R4(26) R4(6)
                INJ4(sk0, s5)
                R4(17) R4(29) R4(16) R4(24)
                INJ4(sk1, s6)
                R4(13) R4(15) R4(26) R4(6)
                INJ4(s3, s7)

                uint32_t vA = (a0 ^ a1) & 0xFFFFFE00u;
                uint32_t vB = (b0 ^ b1) & 0xFFFFFE00u;
                uint32_t vC = (c0 ^ c1) & 0xFFFFFE00u;
                uint32_t vD = (d0 ^ d1) & 0xFFFFFE00u;
                uint32_t pA, pB, pC, pD;
                MADD(pA, vA, kinv); MADD(pB, vB, kinv);
                MADD(pC, vC, kinv); MADD(pD, vD, kinv);

                if (pos) {
                    bpA = max(bpA, pA); bpB = max(bpB, pB);
                    bpC = max(bpC, pC); bpD = max(bpD, pD);
                } else {
                    bnA = max(bnA, pA); bnB = max(bnB, pB);
                    bnC = max(bnC, pC); bnD = max(bnD, pD);
                }
                cntA += AM_THREADS; cntB += AM_THREADS;
                cntC += AM_THREADS; cntD += AM_THREADS;
                kinv -= 16u;
            }
        } else {
            // rare mixed-label group: scalar per-row path
            const int rs[4] = {rA, rB, rC, rD};
            uint32_t* bps[4] = {&bpA, &bpB, &bpC, &bpD};
            uint32_t* bns[4] = {&bnA, &bnB, &bnC, &bnD};
            for (int rr = 0; rr < 4; rr++) {
                const int r = rs[rr];
                const uint32_t myl = slab[r];
                uint32_t cnt = ((uint32_t)r << 13) + (uint32_t)tid;
                uint32_t kinv = 31u << 4;
                uint32_t bp = 0u, bn = 0u;
                #pragma unroll 1
                for (int k = 0; k < 32; k++) {
                    const uint32_t lab = slab[tid + k * AM_THREADS];
                    const bool pos = (lab == myl);
                    const uint32_t pos01 = pos ? 1u : 0u;
                    const uint32_t v = tf_eval1(one, pos01, cnt, n0,n1,n2,n3,n4,n5,n6,n7);
                    uint32_t packed; MADD(packed, v, kinv);
                    if (pos) bp = max(bp, packed); else bn = max(bn, packed);
                    cnt += AM_THREADS;
                    kinv -= 16u;
                }
                *bps[rr] = bp; *bns[rr] = bn;
            }
        }

        // per-row merge: decode packed -> u64 (v23<<13)|(8191-col), reduce, store
        const uint32_t tu = (uint32_t)tid;
        const uint32_t accp[4] = {bpA, bpB, bpC, bpD};
        const uint32_t accn[4] = {bnA, bnB, bnC, bnD};
        const int rows[4] = {rA, rB, rC, rD};
        for (int rr = 0; rr < 4; rr++) {
            const uint32_t kp_ = 31u - ((accp[rr] >> 4) & 31u);
            const uint32_t kn_ = 31u - ((accn[rr] >> 4) & 31u);
            const uint32_t colp = tu + kp_ * AM_THREADS;
            const uint32_t coln = tu + kn_ * AM_THREADS;
            unsigned long long pkp =
                ((unsigned long long)(accp[rr] >> 9) << 13) | (unsigned long long)(8191u - colp);
            unsigned long long pkn =
                ((unsigned long long)(accn[rr] >> 9) << 13) | (unsigned long long)(8191u - coln);
            for (int off = 16; off > 0; off >>= 1) {
                unsigned long long o;
                o = __shfl_down_sync(0xFFFFFFFFu, pkp, off); if (o > pkp) pkp = o;
                o = __shfl_down_sync(0xFFFFFFFFu, pkn, off); if (o > pkn) pkn = o;
            }
            const int w = tid >> 5;
            if ((tid & 31) == 0) { sredp[w] = pkp; sredn[w] = pkn; }
            __syncthreads();
            if (tid == 0) {
                unsigned long long mp = sredp[0], mn = sredn[0];
                #pragma unroll
                for (int i = 1; i < AM_THREADS / 32; i++) {
                    if (sredp[i] > mp) mp = sredp[i];
                    if (sredn[i] > mn) mn = sredn[i];
                }
                g_idx_p[rows[rr]] = 8191 - (int)(mp & 0x1FFFull);
                g_idx_n[rows[rr]] = 8191 - (int)(mn & 0x1FFFull);
            }
        }
        __syncthreads();
    }
}

// Per-row hinge: cos(a,p) - cos(a,n) + margin, clamped at 0.
__global__ void __launch_bounds__(128) loss_kernel(const float* __restrict__ pred) {
    __shared__ float sred[5][4];
    const int r = blockIdx.x;
    const int tid = threadIdx.x;
    const int ip  = g_idx_p[r];
    const int in_ = g_idx_n[r];
    const float* __restrict__ a = pred + (size_t)r   * D;
    const float* __restrict__ p = pred + (size_t)ip  * D;
    const float* __restrict__ n = pred + (size_t)in_ * D;

    float saa = 0.f, spp = 0.f, snn = 0.f, sap = 0.f, san = 0.f;
    for (int j = tid; j < D; j += 128) {
        const float av = a[j], pv = p[j], nv = n[j];
        saa += av * av; spp += pv * pv; snn += nv * nv;
        sap += av * pv; san += av * nv;
    }
    for (int off = 16; off > 0; off >>= 1) {
        saa += __shfl_down_sync(0xFFFFFFFFu, saa, off);
        spp += __shfl_down_sync(0xFFFFFFFFu, spp, off);
        snn += __shfl_down_sync(0xFFFFFFFFu, snn, off);
        sap += __shfl_down_sync(0xFFFFFFFFu, sap, off);
        san += __shfl_down_sync(0xFFFFFFFFu, san, off);
    }
    const int w = tid >> 5;
    if ((tid & 31) == 0) {
        sred[0][w] = saa; sred[1][w] = spp; sred[2][w] = snn;
        sred[3][w] = sap; sred[4][w] = san;
    }
    __syncthreads();
    if (tid == 0) {
        float t0 = 0, t1 = 0, t2 = 0, t3 = 0, t4 = 0;
        #pragma unroll
        for (int i = 0; i < 4; i++) {
            t0 += sred[0][i]; t1 += sred[1][i]; t2 += sred[2][i];
            t3 += sred[3][i]; t4 += sred[4][i];
        }
        const float na = fmaxf(sqrtf(t0), 1e-6f);
        const float np = fmaxf(sqrtf(t1), 1e-6f);
        const float nn = fmaxf(sqrtf(t2), 1e-6f);
        g_rowloss[r] = fmaxf(t3 / (na * np) - t4 / (na * nn) + 0.1f, 0.0f);
    }
}

__global__ void __launch_bounds__(1024) reduce_kernel(float* __restrict__ out) {
    __shared__ float s[1024];
    const int tid = threadIdx.x;
    float v = 0.f;
    for (int i = tid; i < B; i += 1024) v += g_rowloss[i];
    s[tid] = v;
    __syncthreads();
    for (int st = 512; st > 0; st >>= 1) {
        if (tid < st) s[tid] += s[tid + st];
        __syncthreads();
    }
    if (tid == 0) out[0] = s[0] * (1.0f / (float)B);
}

extern "C" void kernel_launch(void* const* d_in, const int* in_sizes, int n_in,
                              void* d_out, int out_size) {
    const float* pred   = (const float*)d_in[0];
    const int*   labels = (const int*)d_in[1];
    float* out = (float*)d_out;

    order_kernel<<<1, 448>>>(labels);
    argmax_kernel<<<AM_GRID, AM_THREADS>>>(labels);
    loss_kernel<<<B, 128>>>(pred);
    reduce_kernel<<<1, 1024>>>(out);
}